// round 7
// baseline (speedup 1.0000x reference)
#include <cuda_runtime.h>

// Shape (N,C,T,V,M) = (256,3,600,25,2), f32.
// Work decomposition: 1 unit = 20 rows = 500 float2. Sample = 90 units.
// Total 23040 units -> 288 blocks x 80 units each (perfect balance, single wave).
#define NB       256
#define VV       25
#define TT       600
#define THREADS  500
#define UPB      80                // units per block
#define BLOCKS   288               // 23040 / 80
#define NTOT     23040000.0f

// Per-block partials for up to 2 samples touched by the block (plain stores).
__device__ float        gA[BLOCKS][2][VV];
__device__ float        gS[BLOCKS][2][VV];
__device__ unsigned int g_count;   // zero at load; reset by finalizer each replay

__global__ __launch_bounds__(THREADS, 2)
void loss_balanced(const float2* __restrict__ x, const float2* __restrict__ y,
                   float* __restrict__ out)
{
    const int b   = blockIdx.x;
    const int tid = threadIdx.x;
    const int v   = tid % VV;
    const int r0  = tid / VV;                  // row offset within a unit (0..19)

    const int u0     = b * UPB;                // first global unit of this block
    const int offset = u0 % 90;                // units into current sample
    int split = 90 - offset;                   // iteration where sample switches
    if (split > UPB) split = UPB;              // block fits in one sample

    const float2* __restrict__ xp = x + (size_t)500 * u0;
    const float2* __restrict__ yp = y + (size_t)500 * u0;

    __shared__ float sA[2][VV];
    __shared__ float sS[2][VV];
    __shared__ bool  sFinal;
    if (tid < 2 * VV) { sA[tid / VV][tid % VV] = 0.0f; sS[tid / VV][tid % VV] = 0.0f; }
    if (tid == 0) sFinal = false;
    __syncthreads();

    // t for this thread at unit j is (20*u0 + r0 + 20*j) mod 600 -> incremental
    int t = (1600 * b + r0) % 600;

    float a0A = 0.0f, a0S = 0.0f;              // first sample's accumulators
    float a1A = 0.0f, a1S = 0.0f;              // second sample's accumulators

    int j = 0;
    #pragma unroll 5
    for (; j < split; ++j) {
        const int idx = tid + j * THREADS;
        const float2 a  = __ldg(&xp[idx]);
        const float2 yv = __ldcs(&yp[idx]);    // read-once stream: evict-first
        const float dx = a.x - yv.x;
        const float dy = a.y - yv.y;
        a0S = fmaf(dx, dx, a0S);
        a0S = fmaf(dy, dy, a0S);
        if (t != TT - 1) {                     // temporal diff within channel; also edge guard
            const float2 bn = __ldg(&xp[idx + VV]);
            a0A += fabsf(bn.x - a.x) + fabsf(bn.y - a.y);
        }
        t += 20; if (t >= TT) t -= TT;
    }
    #pragma unroll 5
    for (; j < UPB; ++j) {
        const int idx = tid + j * THREADS;
        const float2 a  = __ldg(&xp[idx]);
        const float2 yv = __ldcs(&yp[idx]);
        const float dx = a.x - yv.x;
        const float dy = a.y - yv.y;
        a1S = fmaf(dx, dx, a1S);
        a1S = fmaf(dy, dy, a1S);
        if (t != TT - 1) {
            const float2 bn = __ldg(&xp[idx + VV]);
            a1A += fabsf(bn.x - a.x) + fabsf(bn.y - a.y);
        }
        t += 20; if (t >= TT) t -= TT;
    }

    atomicAdd(&sA[0][v], a0A);  atomicAdd(&sS[0][v], a0S);
    atomicAdd(&sA[1][v], a1A);  atomicAdd(&sS[1][v], a1S);
    __syncthreads();

    // Publish both slots (slot 1 is zeros if unused) -- deterministic stores
    if (tid < 2 * VV) {
        const int s = tid / VV, vv = tid % VV;
        gA[b][s][vv] = sA[s][vv];
        gS[b][s][vv] = sS[s][vv];
    }
    __syncthreads();
    if (tid == 0) {
        __threadfence();
        unsigned int prev = atomicAdd(&g_count, 1u);
        sFinal = (prev == BLOCKS - 1);
    }
    __syncthreads();
    if (!sFinal) return;

    // ---- Finalizer (last-arriving block) ----
    __threadfence();
    __shared__ float red[8];
    float part = 0.0f;
    if (tid < NB) {
        const int n   = tid;
        const int blo = (90 * n) / UPB;
        const int bhi = (90 * n + 89) / UPB;   // <= blo+2
        float tot = 0.0f, contrib = 0.0f;
        for (int vv = 0; vv < VV; ++vv) {
            float av = 0.0f, sv = 0.0f;
            for (int bb = blo; bb <= bhi; ++bb) {   // fixed order: deterministic
                const int n0b  = (UPB * bb) / 90;
                const int slot = (n == n0b) ? 0 : 1;
                av += __ldcg(&gA[bb][slot][vv]);
                sv += __ldcg(&gS[bb][slot][vv]);
            }
            tot     += av;
            contrib += av * sv;
        }
        part = (float)VV * contrib / tot;

        // warp reduce over full warps 0..7
        #pragma unroll
        for (int o = 16; o > 0; o >>= 1)
            part += __shfl_xor_sync(0xffffffffu, part, o);
        if ((tid & 31) == 0) red[tid >> 5] = part;
    }
    __syncthreads();
    if (tid < 32) {
        float w = (tid < 8) ? red[tid] : 0.0f;
        #pragma unroll
        for (int o = 4; o > 0; o >>= 1)
            w += __shfl_xor_sync(0xffffffffu, w, o);
        if (tid == 0) {
            out[0]  = w / NTOT;
            g_count = 0u;                      // rearm for next graph replay
            __threadfence();
        }
    }
}

extern "C" void kernel_launch(void* const* d_in, const int* in_sizes, int n_in,
                              void* d_out, int out_size)
{
    (void)in_sizes; (void)n_in; (void)out_size;
    loss_balanced<<<BLOCKS, THREADS>>>((const float2*)d_in[0],
                                       (const float2*)d_in[1],
                                       (float*)d_out);
}